// round 15
// baseline (speedup 1.0000x reference)
#include <cuda_runtime.h>
#include <cuda_bf16.h>
#include <math.h>
#include <stdint.h>

// ---------------- problem constants ----------------
#define S_   2048
#define D_   1024
#define H_   16
#define HD_  64
#define TE_  16
#define TOPK 2
#define ED_  512
#define DS_  2048
#define T_   2048
#define NSLOT (T_*TOPK)
#define EPS_ 1e-5f

// ---------------- scratch (device bss, no allocation) ----------------
__device__ __align__(256) __nv_bfloat16 d_xn_h[(size_t)T_*D_],     d_xn_l[(size_t)T_*D_];
__device__ __align__(256) __nv_bfloat16 d_aw_h[(size_t)3*D_*D_],   d_aw_l[(size_t)3*D_*D_];
__device__ __align__(256) __nv_bfloat16 d_ow_h[(size_t)D_*D_],     d_ow_l[(size_t)D_*D_];
__device__ __align__(256) __nv_bfloat16 d_ao_h[(size_t)T_*D_],     d_ao_l[(size_t)T_*D_];
__device__ __align__(256) __nv_bfloat16 d_xffn_h[(size_t)T_*D_],   d_xffn_l[(size_t)T_*D_];
__device__ __align__(256) __nv_bfloat16 d_upw_h[(size_t)2*DS_*D_], d_upw_l[(size_t)2*DS_*D_];  // interleaved
__device__ __align__(256) __nv_bfloat16 d_dnw_h[(size_t)D_*DS_],   d_dnw_l[(size_t)D_*DS_];
__device__ __align__(256) __nv_bfloat16 d_w12t_h[(size_t)TE_*2*ED_*D_], d_w12t_l[(size_t)TE_*2*ED_*D_]; // interleaved
__device__ __align__(256) __nv_bfloat16 d_w3_h[(size_t)TE_*D_*ED_],     d_w3_l[(size_t)TE_*D_*ED_];
__device__ __align__(256) __nv_bfloat16 d_g_h[(size_t)NSLOT*ED_],  d_g_l[(size_t)NSLOT*ED_];
__device__ __align__(256) __nv_bfloat16 d_gs_h[(size_t)T_*DS_],    d_gs_l[(size_t)T_*DS_];
__device__ __align__(256) __nv_bfloat16 d_q_h[(size_t)T_*D_], d_q_l[(size_t)T_*D_];
__device__ __align__(256) __nv_bfloat16 d_k_h[(size_t)T_*D_], d_k_l[(size_t)T_*D_];
__device__ __align__(256) __nv_bfloat16 d_v_h[(size_t)T_*D_], d_v_l[(size_t)T_*D_];
__device__ __align__(256) float d_qkv[(size_t)T_*3*D_];
__device__ __align__(256) float d_xffn_in[(size_t)T_*D_];
__device__ __align__(256) float d_xffn[(size_t)T_*D_];
__device__ __align__(256) float d_y[(size_t)T_*D_];
__device__ __align__(256) float d_ysh[(size_t)T_*D_];
__device__ float d_scores[NSLOT];
__device__ int   d_counts[TE_];
__device__ int   d_list[TE_*NSLOT];

// ---------------- helpers ----------------
__device__ __forceinline__ void f2hilo(float x, __nv_bfloat16* h, __nv_bfloat16* l) {
    __nv_bfloat16 hh = __float2bfloat16(x);
    *h = hh;
    *l = __float2bfloat16(x - __bfloat162float(hh));
}
__device__ __forceinline__ uint32_t bpack(__nv_bfloat16 a, __nv_bfloat16 b) {
    uint16_t ua = *(uint16_t*)&a, ub = *(uint16_t*)&b;
    return ((uint32_t)ub << 16) | ua;
}
__device__ __forceinline__ uint32_t packh(float x, float y, uint32_t* lo) {
    __nv_bfloat16 hx = __float2bfloat16(x), hy = __float2bfloat16(y);
    __nv_bfloat16 lx = __float2bfloat16(x - __bfloat162float(hx));
    __nv_bfloat16 ly = __float2bfloat16(y - __bfloat162float(hy));
    *lo = bpack(lx, ly);
    return bpack(hx, hy);
}
__device__ __forceinline__ float block_reduce_sum(float v, float* sh) {
    __syncthreads();
    int lane = threadIdx.x & 31, wid = threadIdx.x >> 5;
#pragma unroll
    for (int o = 16; o; o >>= 1) v += __shfl_xor_sync(0xffffffffu, v, o);
    if (lane == 0) sh[wid] = v;
    __syncthreads();
    int nw = blockDim.x >> 5;
    v = (threadIdx.x < nw) ? sh[threadIdx.x] : 0.f;
    if (wid == 0) {
#pragma unroll
        for (int o = 16; o; o >>= 1) v += __shfl_xor_sync(0xffffffffu, v, o);
        if (lane == 0) sh[0] = v;
    }
    __syncthreads();
    return sh[0];
}
__device__ __forceinline__ void mma16816(float* d, const uint32_t* a, const uint32_t* b) {
    asm volatile(
        "mma.sync.aligned.m16n8k16.row.col.f32.bf16.bf16.f32 "
        "{%0,%1,%2,%3}, {%4,%5,%6,%7}, {%8,%9}, {%0,%1,%2,%3};"
        : "+f"(d[0]), "+f"(d[1]), "+f"(d[2]), "+f"(d[3])
        : "r"(a[0]), "r"(a[1]), "r"(a[2]), "r"(a[3]), "r"(b[0]), "r"(b[1]));
}
__device__ __forceinline__ void ldsm_x4(uint32_t* r, uint32_t addr) {
    asm volatile("ldmatrix.sync.aligned.m8n8.x4.shared.b16 {%0,%1,%2,%3}, [%4];"
        : "=r"(r[0]), "=r"(r[1]), "=r"(r[2]), "=r"(r[3]) : "r"(addr));
}
__device__ __forceinline__ void ldsm_x4t(uint32_t* r, uint32_t addr) {
    asm volatile("ldmatrix.sync.aligned.m8n8.x4.trans.shared.b16 {%0,%1,%2,%3}, [%4];"
        : "=r"(r[0]), "=r"(r[1]), "=r"(r[2]), "=r"(r[3]) : "r"(addr));
}
__device__ __forceinline__ void cpa16(uint32_t dst, const void* src, int sb) {
    asm volatile("cp.async.cg.shared.global [%0], [%1], 16, %2;"
                 :: "r"(dst), "l"(src), "r"(sb));
}
__device__ __forceinline__ void cpa_commit() { asm volatile("cp.async.commit_group;"); }
template<int N> __device__ __forceinline__ void cpa_wait() {
    asm volatile("cp.async.wait_group %0;" :: "n"(N));
}

// ---------------- conversion kernels (vectorized) ----------------
__global__ void conv_hilo_kernel(const float4* __restrict__ src, uint2* __restrict__ hi,
                                 uint2* __restrict__ lo, size_t n4) {
    for (size_t i = (size_t)blockIdx.x * blockDim.x + threadIdx.x; i < n4;
         i += (size_t)gridDim.x * blockDim.x) {
        float4 v = src[i];
        __nv_bfloat16 h0, l0, h1, l1, h2, l2, h3, l3;
        f2hilo(v.x, &h0, &l0); f2hilo(v.y, &h1, &l1);
        f2hilo(v.z, &h2, &l2); f2hilo(v.w, &h3, &l3);
        uint2 ho, lw;
        ho.x = bpack(h0, h1); ho.y = bpack(h2, h3);
        lw.x = bpack(l0, l1); lw.y = bpack(l2, l3);
        hi[i] = ho; lo[i] = lw;
    }
}

// interleave ffn_up rows: dest row 2j = src row j (W1), dest row 2j+1 = src row DS+j (W2)
__global__ void conv_hilo_ilv_kernel(const float4* __restrict__ src, uint2* __restrict__ hi,
                                     uint2* __restrict__ lo) {
    size_t n4 = (size_t)2 * DS_ * D_ / 4;
    size_t rowq = D_ / 4;
    for (size_t i = (size_t)blockIdx.x * blockDim.x + threadIdx.x; i < n4;
         i += (size_t)gridDim.x * blockDim.x) {
        size_t r = i / rowq, c = i % rowq;
        size_t sr = (r & 1) ? ((size_t)DS_ + (r >> 1)) : (r >> 1);
        float4 v = src[sr * rowq + c];
        __nv_bfloat16 h0, l0, h1, l1, h2, l2, h3, l3;
        f2hilo(v.x, &h0, &l0); f2hilo(v.y, &h1, &l1);
        f2hilo(v.z, &h2, &l2); f2hilo(v.w, &h3, &l3);
        uint2 ho, lw;
        ho.x = bpack(h0, h1); ho.y = bpack(h2, h3);
        lw.x = bpack(l0, l1); lw.y = bpack(l2, l3);
        hi[i] = ho; lo[i] = lw;
    }
}

// experts W1/W2 [m][e][k=D][n=ED] -> w12t [e][2n+m][k] hi/lo (interleaved for swiglu epi)
__global__ void transpose_w12_kernel(const float* __restrict__ experts) {
    __shared__ float tile[64][33];
    int e = blockIdx.z;
    int n0 = blockIdx.x * 32, k0 = blockIdx.y * 64;
    int m = n0 >> 9, c0 = n0 & 511;
    for (int kk = threadIdx.y; kk < 64; kk += 8)
        tile[kk][threadIdx.x] =
            experts[((size_t)(m * TE_ + e) * D_ + k0 + kk) * ED_ + c0 + threadIdx.x];
    __syncthreads();
    for (int ny = threadIdx.y; ny < 32; ny += 8) {
        int ng = n0 + ny;
        int mm = ng >> 9, cc = ng & 511;
        int rr = 2 * cc + mm;
        float va = tile[threadIdx.x * 2][ny];
        float vb = tile[threadIdx.x * 2 + 1][ny];
        __nv_bfloat16 ha, la, hb, lb;
        f2hilo(va, &ha, &la); f2hilo(vb, &hb, &lb);
        size_t o = ((size_t)e << 20) + (size_t)rr * 1024 + k0 + threadIdx.x * 2;
        *(uint32_t*)(d_w12t_h + o) = bpack(ha, hb);
        *(uint32_t*)(d_w12t_l + o) = bpack(la, lb);
    }
}

// ---------------- rmsnorm (fp32 optional + hi/lo) ----------------
__global__ void rmsnorm_kernel(const float* __restrict__ x, const float* __restrict__ w,
                               float* __restrict__ outf, __nv_bfloat16* __restrict__ oh,
                               __nv_bfloat16* __restrict__ ol) {
    int row = blockIdx.x;
    const float* xr = x + (size_t)row * D_;
    float ss = 0.f;
    for (int i = threadIdx.x; i < D_; i += blockDim.x) { float v = xr[i]; ss += v * v; }
    __shared__ float sh[32];
    float tot = block_reduce_sum(ss, sh);
    float rinv = rsqrtf(tot / (float)D_ + EPS_);
    for (int i = threadIdx.x; i < D_; i += blockDim.x) {
        float v = xr[i] * rinv * w[i];
        size_t o = (size_t)row * D_ + i;
        if (outf) outf[o] = v;
        f2hilo(v, oh + o, ol + o);
    }
}

// ---------------- warp-MMA split-bf16 GEMM: C[M,N] = A @ B^T ----------------
// EPI: 0 = fp32 C, 1 = fp32 C + residual, 2 = swiglu pair -> bf16 hi/lo (C=Gh, Res=Gl),
//      3 = routed combine: atomicAdd(d_y[tok], score[slot] * v)
// Inner loop: 3 interleaved MMA passes (hh, lh, hl) — 16 independent accumulators
// between dependent updates; per-acc accumulation order unchanged.
#define SD    40
#define STG_E (4*128*SD)
#define GEMM_SMEM (4*STG_E*2)

template<int GATHER, int EPI>
__global__ void __launch_bounds__(256, 1) gemm_mma(
    const __nv_bfloat16* __restrict__ Ah, const __nv_bfloat16* __restrict__ Al,
    const __nv_bfloat16* __restrict__ Bh, const __nv_bfloat16* __restrict__ Bl,
    float* __restrict__ C, const float* __restrict__ Res,
    int N, int K, long long bstride)
{
    __shared__ int s_row[128];
    __shared__ int s_out[128];
    int tid = threadIdx.x, wid = tid >> 5, lid = tid & 31;
    if (GATHER) {
        int e = blockIdx.z, cnt = d_counts[e];
        if ((int)blockIdx.y * 128 >= cnt) return;
        if (tid < 128) {
            int r = blockIdx.y * 128 + tid;
            int sl = (r < cnt) ? d_list[e * NSLOT + r] : -1;
            s_out[tid] = sl;
            s_row[tid] = (sl < 0) ? -1 : (GATHER == 1 ? (sl >> 1) : sl);
        }
        Bh += (size_t)blockIdx.z * bstride;
        Bl += (size_t)blockIdx.z * bstride;
    } else if (tid < 128) {
        int r = blockIdx.y * 128 + tid;
        s_row[tid] = r; s_out[tid] = r;
    }
    extern __shared__ __nv_bfloat16 sm[];
    uint32_t smb = (uint32_t)__cvta_generic_to_shared(sm);
    int n0 = blockIdx.x * 128;
    int NC = K >> 5;
    __syncthreads();

    int lrow = tid >> 2, lq = tid & 3;
    int arow0 = s_row[lrow];
    const __nv_bfloat16* asrc_h = Ah + (size_t)(arow0 < 0 ? 0 : arow0) * K + lq * 8;
    const __nv_bfloat16* asrc_l = Al + (size_t)(arow0 < 0 ? 0 : arow0) * K + lq * 8;
    const __nv_bfloat16* bsrc_h = Bh + (size_t)(n0 + lrow) * K + lq * 8;
    const __nv_bfloat16* bsrc_l = Bl + (size_t)(n0 + lrow) * K + lq * 8;
    int asb = (arow0 < 0) ? 0 : 16;
    int arow1 = s_row[lrow + 64];
    const __nv_bfloat16* asrc2_h = Ah + (size_t)(arow1 < 0 ? 0 : arow1) * K + lq * 8;
    const __nv_bfloat16* asrc2_l = Al + (size_t)(arow1 < 0 ? 0 : arow1) * K + lq * 8;
    const __nv_bfloat16* bsrc2_h = Bh + (size_t)(n0 + lrow + 64) * K + lq * 8;
    const __nv_bfloat16* bsrc2_l = Bl + (size_t)(n0 + lrow + 64) * K + lq * 8;
    int asb2 = (arow1 < 0) ? 0 : 16;
    uint32_t o1 = (uint32_t)((lrow * SD + lq * 8) << 1);
    uint32_t o2 = (uint32_t)(((lrow + 64) * SD + lq * 8) << 1);
    const uint32_t OFF_AL = (uint32_t)((128 * SD) << 1);
    const uint32_t OFF_BH = (uint32_t)((2 * 128 * SD) << 1);
    const uint32_t OFF_BL = (uint32_t)((3 * 128 * SD) << 1);

    auto issue = [&](int c, int buf) {
        uint32_t st = smb + (uint32_t)(buf * STG_E * 2);
        int kc = c << 5;
        cpa16(st + o1, asrc_h + kc, asb);
        cpa16(st + OFF_AL + o1, asrc_l + kc, asb);
        cpa16(st + OFF_BH + o1, bsrc_h + kc, 16);
        cpa16(st + OFF_BL + o1, bsrc_l + kc, 16);
        cpa16(st + o2, asrc2_h + kc, asb2);
        cpa16(st + OFF_AL + o2, asrc2_l + kc, asb2);
        cpa16(st + OFF_BH + o2, bsrc2_h + kc, 16);
        cpa16(st + OFF_BL + o2, bsrc2_l + kc, 16);
        cpa_commit();
    };

    int wm = wid & 1, wn = wid >> 1;
    int r = lid >> 2, c2 = (lid & 3) << 1;
    uint32_t a_lane = (uint32_t)(((lid & 15) * SD + ((lid >> 4) << 3)) << 1);
    uint32_t b_lane = (uint32_t)((((((lid >> 4) << 3) + (lid & 7)) * SD) + (((lid >> 3) & 1) << 3)) << 1);
    float acc[4][4][4] = {};

    issue(0, 0);
    if (NC > 1) issue(1, 1);
    if (NC > 2) issue(2, 2);
    for (int c = 0; c < NC; c++) {
        int buf = c & 3;
        if (c + 2 < NC) cpa_wait<2>();
        else if (c + 1 < NC) cpa_wait<1>();
        else cpa_wait<0>();
        __syncthreads();
        uint32_t base = smb + (uint32_t)(buf * STG_E * 2);
#pragma unroll
        for (int ks = 0; ks < 2; ks++) {
            uint32_t kb = (uint32_t)(ks << 5);
            uint32_t ah[4][4], al[4][4];
#pragma unroll
            for (int mt = 0; mt < 4; mt++) {
                uint32_t ab = base + (uint32_t)(((wm * 64 + mt * 16) * SD) << 1) + kb + a_lane;
                ldsm_x4(ah[mt], ab);
                ldsm_x4(al[mt], ab + OFF_AL);
            }
            uint32_t bh[4][2], bl[4][2];
#pragma unroll
            for (int p = 0; p < 2; p++) {
                uint32_t bb = base + OFF_BH
                            + (uint32_t)(((wn * 32 + p * 16) * SD) << 1) + kb + b_lane;
                uint32_t t[4];
                ldsm_x4(t, bb);
                bh[2*p][0] = t[0]; bh[2*p][1] = t[1];
                bh[2*p+1][0] = t[2]; bh[2*p+1][1] = t[3];
                ldsm_x4(t, bb + OFF_AL);
                bl[2*p][0] = t[0]; bl[2*p][1] = t[1];
                bl[2*p+1][0] = t[2]; bl[2*p+1][1] = t[3];
            }
            // pass 1: hi*hi (16 independent MMAs)
#pragma unroll
            for (int nt = 0; nt < 4; nt++)
#pragma unroll
                for (int mt = 0; mt < 4; mt++)
                    mma16816(acc[mt][nt], ah[mt], bh[nt]);
            // pass 2: lo*hi
#pragma unroll
            for (int nt = 0; nt < 4; nt++)
#pragma unroll
                for (int mt = 0; mt < 4; mt++)
                    mma16816(acc[mt][nt], al[mt], bh[nt]);
            // pass 3: hi*lo
#pragma unroll
            for (int nt = 0; nt < 4; nt++)
#pragma unroll
                for (int mt = 0; mt < 4; mt++)
                    mma16816(acc[mt][nt], ah[mt], bl[nt]);
        }
        if (c + 3 < NC) issue(c + 3, (c + 3) & 3);
    }

    // epilogue
#pragma unroll
    for (int mt = 0; mt < 4; mt++) {
        int rloc0 = wm * 64 + mt * 16 + r;
#pragma unroll
        for (int half = 0; half < 2; half++) {
            int rloc = rloc0 + half * 8;
            int outr = s_out[rloc];
            if (GATHER && outr < 0) continue;
            if (EPI == 2) {
                __nv_bfloat16* Gh = (__nv_bfloat16*)C;
                __nv_bfloat16* Gl = (__nv_bfloat16*)(void*)Res;
                int hn = N >> 1;
#pragma unroll
                for (int nt = 0; nt < 4; nt++) {
                    int col = wn * 32 + nt * 8 + c2;
                    float v0 = acc[mt][nt][half * 2 + 0];
                    float v1 = acc[mt][nt][half * 2 + 1];
                    float g = (v0 / (1.f + __expf(-v0))) * v1;
                    size_t oo = (size_t)outr * hn + ((n0 + col) >> 1);
                    f2hilo(g, Gh + oo, Gl + oo);
                }
            } else if (EPI == 3) {
                int tok = outr >> 1;
                float sc = d_scores[outr];
                float* crow = C + (size_t)tok * N + n0;
#pragma unroll
                for (int nt = 0; nt < 4; nt++) {
                    int col = wn * 32 + nt * 8 + c2;
                    atomicAdd(crow + col,     sc * acc[mt][nt][half * 2 + 0]);
                    atomicAdd(crow + col + 1, sc * acc[mt][nt][half * 2 + 1]);
                }
            } else {
                float* crow = C + (size_t)outr * N + n0;
#pragma unroll
                for (int nt = 0; nt < 4; nt++) {
                    int col = wn * 32 + nt * 8 + c2;
                    float v0 = acc[mt][nt][half * 2 + 0];
                    float v1 = acc[mt][nt][half * 2 + 1];
                    if (EPI == 1) {
                        const float* rrow = Res + (size_t)outr * N + n0;
                        v0 += rrow[col]; v1 += rrow[col + 1];
                    }
                    float2 fv = make_float2(v0, v1);
                    *(float2*)(crow + col) = fv;
                }
            }
        }
    }
}

// ---------------- RoPE + convert: qkv fp32 -> q/k/v bf16 hi/lo ----------------
__global__ void rope_conv_kernel(const float* __restrict__ qkv) {
    int s = blockIdx.x;
    int i = threadIdx.x & 31;
    float inv = powf(10000.0f, -(float)i / 32.0f);
    float fr = (float)s * inv;
    float c = cosf(fr), sn = sinf(fr);
    for (int h = threadIdx.x >> 5; h < H_; h += 8) {
        const float* q = qkv + (size_t)s * 3 * D_ + h * HD_;
        const float* k = q + D_;
        const float* v = q + 2 * D_;
        size_t o = (size_t)s * D_ + h * HD_ + i;
        float q1 = q[i], q2 = q[i + 32];
        f2hilo(q1 * c + q2 * sn,  d_q_h + o,      d_q_l + o);
        f2hilo(-q1 * sn + q2 * c, d_q_h + o + 32, d_q_l + o + 32);
        float k1 = k[i], k2 = k[i + 32];
        f2hilo(k1 * c + k2 * sn,  d_k_h + o,      d_k_l + o);
        f2hilo(-k1 * sn + k2 * c, d_k_h + o + 32, d_k_l + o + 32);
        f2hilo(v[i],      d_v_h + o,      d_v_l + o);
        f2hilo(v[i + 32], d_v_h + o + 32, d_v_l + o + 32);
    }
}

// ---------------- tensor-core flash attention: 128 q-rows/CTA, 8 warps ----------------
// heavy CTAs first; 3 interleaved MMA passes in S and O loops.
#define ASD 72
#define AMAT (64*ASD)
#define AT2_SMEM ((4 + 12)*AMAT*2)
__global__ void __launch_bounds__(256) flash_attn_tc(int dummy) {
    extern __shared__ __nv_bfloat16 asm_[];
    uint32_t bQ = (uint32_t)__cvta_generic_to_shared(asm_);
    const uint32_t OFF1 = (uint32_t)(AMAT << 1);
    const uint32_t QL_OFF = 2 * OFF1;
    int bx = gridDim.x - 1 - blockIdx.x, h = blockIdx.y;
    int tid = threadIdx.x, wid = tid >> 5, lid = tid & 31;
    int q0 = bx * 128;
    int ktmax = 2 * bx + 1;

    {
        int lrow = tid >> 1, lc0 = (tid & 1) * 32;
        const __nv_bfloat16* qh = d_q_h + (size_t)(q0 + lrow) * D_ + h * HD_ + lc0;
        const __nv_bfloat16* ql = d_q_l + (size_t)(q0 + lrow) * D_ + h * HD_ + lc0;
#pragma unroll
        for (int j = 0; j < 4; j++) {
            uint32_t off = (uint32_t)((lrow * ASD + lc0 + j * 8) << 1);
            cpa16(bQ + off, qh + j * 8, 16);
            cpa16(bQ + QL_OFF + off, ql + j * 8, 16);
        }
    }
    int lrowK = tid >> 2, lqK = tid & 3;
    auto issueKV = [&](int kt, int s) {
        uint32_t st = bQ + (uint32_t)((4 + 4 * s) * AMAT * 2);
        size_t src = (size_t)(kt * 64 + lrowK) * D_ + h * HD_ + lqK * 16;
#pragma unroll
        for (int j = 0; j < 2; j++) {
            uint32_t off = (uint32_t)((lrowK * ASD + lqK * 16 + j * 8) << 1);
            cpa16(st + off,            d_k_h + src + j * 8, 16);
            cpa16(st + OFF1 + off,     d_k_l + src + j * 8, 16);
            cpa16(st + 2 * OFF1 + off, d_v_h + src + j * 8, 16);
            cpa16(st + 3 * OFF1 + off, d_v_l + src + j * 8, 16);
        }
        cpa_commit();
    };
    issueKV(0, 0);
    issueKV(1, 1);

    uint32_t a_lane = (uint32_t)(((lid & 15) * ASD + ((lid >> 4) << 3)) << 1);
    uint32_t b_lane = (uint32_t)((((((lid >> 4) << 3) + (lid & 7)) * ASD) + (((lid >> 3) & 1) << 3)) << 1);
    uint32_t v_lane = (uint32_t)((((lid & 7) + (((lid >> 3) & 1) << 3)) * ASD + ((lid >> 4) << 3)) << 1);
    int ra = lid >> 2, c2 = (lid & 3) << 1;
    int ga = q0 + wid * 16 + ra, gb = ga + 8;

    float m0 = -1e30f, m1 = -1e30f, l0 = 0.f, l1 = 0.f;
    float O[8][4] = {};

    for (int kt = 0; kt <= ktmax; kt++) {
        if (kt + 1 <= ktmax) cpa_wait<1>(); else cpa_wait<0>();
        __syncthreads();
        uint32_t bK = bQ + (uint32_t)((4 + 4 * (kt % 3)) * AMAT * 2);
        uint32_t bV = bK + 2 * OFF1;

        float S[8][4] = {};
#pragma unroll
        for (int ks = 0; ks < 4; ks++) {
            uint32_t kb = (uint32_t)(ks << 5);
            uint32_t ah[4], al[4];
            uint32_t ab = (uint32_t)(((wid * 16) * ASD) << 1) + kb + a_lane;
            ldsm_x4(ah, bQ + ab);
            ldsm_x4(al, bQ + QL_OFF + ab);
            uint32_t bh[8][2], bl[8][2];
#pragma unroll
            for (int p = 0; p < 4; p++) {
                uint32_t bb = (uint32_t)(((p * 16) * ASD) << 1) + kb + b_lane;
                uint32_t t[4];
                ldsm_x4(t, bK + bb);
                bh[2*p][0] = t[0]; bh[2*p][1] = t[1];
                bh[2*p+1][0] = t[2]; bh[2*p+1][1] = t[3];
                ldsm_x4(t, bK + OFF1 + bb);
                bl[2*p][0] = t[0]; bl[2*p][1] = t[1];
                bl[2*p+1][0] = t[2]; bl[2*p+1][1] = t[3];
            }
#pragma unroll
            for (int t = 0; t < 8; t++) mma16816(S[t], ah, bh[t]);
#pragma unroll
            for (int t = 0; t < 8; t++) mma16816(S[t], al, bh[t]);
#pragma unroll
            for (int t = 0; t < 8; t++) mma16816(S[t], ah, bl[t]);
        }
        bool diag = (kt >= 2 * bx);
#pragma unroll
        for (int t = 0; t < 8; t++) {
            int col = kt * 64 + t * 8 + c2;
            S[t][0] *= 0.125f; S[t][1] *= 0.125f; S[t][2] *= 0.125f; S[t][3] *= 0.125f;
            if (diag) {
                if (col     > ga) S[t][0] = -1e30f;
                if (col + 1 > ga) S[t][1] = -1e30f;
                if (col     > gb) S[t][2] = -1e30f;
                if (col + 1 > gb) S[t][3] = -1e30f;
            }
        }
        float mxa = -1e30f, mxb = -1e30f;
#pragma unroll
        for (int t = 0; t < 8; t++) {
            mxa = fmaxf(mxa, fmaxf(S[t][0], S[t][1]));
            mxb = fmaxf(mxb, fmaxf(S[t][2], S[t][3]));
        }
        mxa = fmaxf(mxa, __shfl_xor_sync(0xffffffffu, mxa, 1));
        mxa = fmaxf(mxa, __shfl_xor_sync(0xffffffffu, mxa, 2));
        mxb = fmaxf(mxb, __shfl_xor_sync(0xffffffffu, mxb, 1));
        mxb = fmaxf(mxb, __shfl_xor_sync(0xffffffffu, mxb, 2));
        float nma = fmaxf(m0, mxa), nmb = fmaxf(m1, mxb);
        float faca = __expf(m0 - nma), facb = __expf(m1 - nmb);
        m0 = nma; m1 = nmb;
        float suma = 0.f, sumb = 0.f;
#pragma unroll
        for (int t = 0; t < 8; t++) {
            S[t][0] = __expf(S[t][0] - nma); suma += S[t][0];
            S[t][1] = __expf(S[t][1] - nma); suma += S[t][1];
            S[t][2] = __expf(S[t][2] - nmb); sumb += S[t][2];
            S[t][3] = __expf(S[t][3] - nmb); sumb += S[t][3];
        }
        suma += __shfl_xor_sync(0xffffffffu, suma, 1);
        suma += __shfl_xor_sync(0xffffffffu, suma, 2);
        sumb += __shfl_xor_sync(0xffffffffu, sumb, 1);
        sumb += __shfl_xor_sync(0xffffffffu, sumb, 2);
        l0 = l0 * faca + suma; l1 = l1 * facb + sumb;
#pragma unroll
        for (int t = 0; t < 8; t++) {
            O[t][0] *= faca; O[t][1] *= faca; O[t][2] *= facb; O[t][3] *= facb;
        }
#pragma unroll
        for (int ks = 0; ks < 4; ks++) {
            uint32_t ph[4], pl[4];
            ph[0] = packh(S[2*ks][0],   S[2*ks][1],   &pl[0]);
            ph[1] = packh(S[2*ks][2],   S[2*ks][3],   &pl[1]);
            ph[2] = packh(S[2*ks+1][0], S[2*ks+1][1], &pl[2]);
            ph[3] = packh(S[2*ks+1][2], S[2*ks+1][3], &pl[3]);
            uint32_t vh[8][2], vl[8][2];
#pragma unroll
            for (int p = 0; p < 4; p++) {
                uint32_t vb = (uint32_t)(((16 * ks) * ASD + 16 * p) << 1) + v_lane;
                uint32_t t[4];
                ldsm_x4t(t, bV + vb);
                vh[2*p][0] = t[0]; vh[2*p][1] = t[1];
                vh[2*p+1][0] = t[2]; vh[2*p+1][1] = t[3];
                ldsm_x4t(t, bV + OFF1 + vb);
                vl[2*p][0] = t[0]; vl[2*p][1] = t[1];
                vl[2*p+1][0] = t[2]; vl[2*p+1][1] = t[3];
            }
#pragma unroll
            for (int t = 0; t < 8; t++) mma16816(O[t], ph, vh[t]);
#pragma unroll
            for (int t = 0; t < 8; t++) mma16816(O[t], pl, vh[t]);
#pragma unroll
            for (int t = 0; t < 8; t++) mma16816(O[t], ph, vl[t]);
        }
        if (kt + 2 <= ktmax) issueKV(kt + 2, (kt + 2) % 3);
    }
    float il0 = 1.0f / l0, il1 = 1.0f / l1;
#pragma unroll
    for (int t = 0; t < 8; t++) {
        int col = h * HD_ + t * 8 + c2;
        size_t r0 = (size_t)ga * D_ + col;
        size_t r1 = (size_t)gb * D_ + col;
        f2hilo(O[t][0] * il0, d_ao_h + r0,     d_ao_l + r0);
        f2hilo(O[t][1] * il0, d_ao_h + r0 + 1, d_ao_l + r0 + 1);
        f2hilo(O[t][2] * il1, d_ao_h + r1,     d_ao_l + r1);
        f2hilo(O[t][3] * il1, d_ao_h + r1 + 1, d_ao_l + r1 + 1);
    }
}

// ---------------- router ----------------
__global__ void router_kernel(const float* __restrict__ xffn, const float* __restrict__ keys,
                              const int* __restrict__ idx, const float* __restrict__ vals,
                              const float* __restrict__ bias) {
    int t = blockIdx.x, lane = threadIdx.x;
    int e0 = idx[t * 2], e1 = idx[t * 2 + 1];
    const float* xr = xffn + (size_t)t * D_;
    float s0 = 0.f, s1 = 0.f;
    for (int d = lane; d < D_; d += 32) {
        float x = xr[d];
        s0 += x * keys[d * TE_ + e0];
        s1 += x * keys[d * TE_ + e1];
    }
#pragma unroll
    for (int o = 16; o; o >>= 1) {
        s0 += __shfl_xor_sync(0xffffffffu, s0, o);
        s1 += __shfl_xor_sync(0xffffffffu, s1, o);
    }
    if (lane == 0) {
        float v0 = vals[t * 2] + s0 + bias[e0];
        float v1 = vals[t * 2 + 1] + s1 + bias[e1];
        float mm = fmaxf(v0, v1);
        float a = expf(v0 - mm), b = expf(v1 - mm);
        float inv = 1.0f / (a + b);
        d_scores[t * 2] = a * inv;
        d_scores[t * 2 + 1] = b * inv;
    }
}

__global__ void zero_counts_kernel() {
    if (threadIdx.x < TE_) d_counts[threadIdx.x] = 0;
}
__global__ void scatter_kernel(const int* __restrict__ idx) {
    int slot = blockIdx.x * blockDim.x + threadIdx.x;
    if (slot < NSLOT) {
        int e = idx[slot];
        int p = atomicAdd(&d_counts[e], 1);
        d_list[e * NSLOT + p] = slot;
    }
}

// ---------------- final combine (coeff folded in) ----------------
__global__ void final_kernel(const float* __restrict__ sharedw, const float* __restrict__ coeff,
                             float* __restrict__ out) {
    int t = blockIdx.x;
    const float* ysh = d_ysh + (size_t)t * D_;
    float ss = 0.f;
    for (int i = threadIdx.x; i < D_; i += blockDim.x) { float v = ysh[i]; ss += v * v; }
    __shared__ float sh[32];
    float tot = block_reduce_sum(ss, sh);
    float rinv = rsqrtf(tot / (float)D_ + EPS_);
    const float* yr = d_y + (size_t)t * D_;
    const float* xr = d_xffn_in + (size_t)t * D_;
    float* o = out + (size_t)t * D_;
    for (int i = threadIdx.x; i < D_; i += blockDim.x)
        o[i] = yr[i] * coeff[i] + ysh[i] * rinv * sharedw[i] + xr[i];
}

// ---------------- host launch ----------------
static void* sym(const void* s) { void* p = nullptr; cudaGetSymbolAddress(&p, s); return p; }

static cudaStream_t g_sA = nullptr, g_sB = nullptr;
static cudaEvent_t  g_evF, g_evAW, g_evOW, g_evWTS, g_evX, g_evB;
static bool g_init = false;

extern "C" void kernel_launch(void* const* d_in, const int* in_sizes, int n_in,
                              void* d_out, int out_size) {
    const float* x_input      = (const float*)d_in[0];
    const int*   indices      = (const int*)  d_in[1];
    const float* values       = (const float*)d_in[2];
    const float* attn_w       = (const float*)d_in[3];
    const float* attn_o_w     = (const float*)d_in[4];
    const float* attn_norm_w  = (const float*)d_in[5];
    const float* ffn_norm_w   = (const float*)d_in[6];
    const float* ffn_experts  = (const float*)d_in[7];
    const float* main_keys    = (const float*)d_in[8];
    const float* main_bias    = (const float*)d_in[9];
    const float* output_coeff = (const float*)d_in[10];
    const float* ffn_up_w     = (const float*)d_in[11];
    const float* ffn_down_w   = (const float*)d_in[12];
    const float* shared_norm_w= (const float*)d_in[13];
    float* out = (float*)d_out;

    if (!g_init) {
        g_init = true;
        cudaStreamCreateWithFlags(&g_sA, cudaStreamNonBlocking);
        cudaStreamCreateWithFlags(&g_sB, cudaStreamNonBlocking);
        cudaEventCreateWithFlags(&g_evF,   cudaEventDisableTiming);
        cudaEventCreateWithFlags(&g_evAW,  cudaEventDisableTiming);
        cudaEventCreateWithFlags(&g_evOW,  cudaEventDisableTiming);
        cudaEventCreateWithFlags(&g_evWTS, cudaEventDisableTiming);
        cudaEventCreateWithFlags(&g_evX,   cudaEventDisableTiming);
        cudaEventCreateWithFlags(&g_evB,   cudaEventDisableTiming);
        cudaFuncSetAttribute((const void*)gemm_mma<0,0>, cudaFuncAttributeMaxDynamicSharedMemorySize, GEMM_SMEM);
        cudaFuncSetAttribute((const void*)gemm_mma<0,1>, cudaFuncAttributeMaxDynamicSharedMemorySize, GEMM_SMEM);
        cudaFuncSetAttribute((const void*)gemm_mma<0,2>, cudaFuncAttributeMaxDynamicSharedMemorySize, GEMM_SMEM);
        cudaFuncSetAttribute((const void*)gemm_mma<1,2>, cudaFuncAttributeMaxDynamicSharedMemorySize, GEMM_SMEM);
        cudaFuncSetAttribute((const void*)gemm_mma<2,3>, cudaFuncAttributeMaxDynamicSharedMemorySize, GEMM_SMEM);
        cudaFuncSetAttribute((const void*)flash_attn_tc, cudaFuncAttributeMaxDynamicSharedMemorySize, AT2_SMEM);
    }
    cudaStream_t sA = g_sA, sB = g_sB;
    cudaEvent_t evF = g_evF, evAW = g_evAW, evOW = g_evOW, evWTS = g_evWTS, evX = g_evX, evB = g_evB;

    __nv_bfloat16 *p_xn_h=(__nv_bfloat16*)sym(d_xn_h), *p_xn_l=(__nv_bfloat16*)sym(d_xn_l);
    __nv_bfloat16 *p_aw_h=(__nv_bfloat16*)sym(d_aw_h), *p_aw_l=(__nv_bfloat16*)sym(d_aw_l);
    __nv_bfloat16 *p_ow_h=(__nv_bfloat16*)sym(d_ow_h), *p_ow_l=(__nv_bfloat16*)sym(d_ow_l);
    __nv_bfloat16 *p_ao_h=(__nv_bfloat16*)sym(d_ao_h), *p_ao_l=(__nv_bfloat16*)sym(d_ao_l);
    __nv_bfloat16 *p_xf_h=(__nv_bfloat16*)sym(d_xffn_h), *p_xf_l=(__nv_bfloat16*)sym(d_xffn_l);
    __nv_bfloat16 *p_uw_h=(__nv_bfloat16*)sym(d_upw_h), *p_uw_l=(__nv_bfloat16*)sym(d_upw_l);
    __nv_bfloat16 *p_dw_h=(__nv_bfloat16*)sym(d_dnw_h), *p_dw_l=(__nv_bfloat16*)sym(d_dnw_l);
    __nv_bfloat16 *p_w12_h=(__nv_bfloat16*)sym(d_w12t_h), *p_w12_l=(__nv_bfloat16*)sym(d_w12t_l);
    __nv_bfloat16 *p_w3_h=(__nv_bfloat16*)sym(d_w3_h), *p_w3_l=(__nv_bfloat16*)sym(d_w3_l);
    __nv_bfloat16 *p_g_h=(__nv_bfloat16*)sym(d_g_h), *p_g_l=(__nv_bfloat16*)sym(d_g_l);
    __nv_bfloat16 *p_gs_h=(__nv_bfloat16*)sym(d_gs_h), *p_gs_l=(__nv_bfloat16*)sym(d_gs_l);
    float *p_qkv=(float*)sym(d_qkv), *p_xffn_in=(float*)sym(d_xffn_in), *p_xffn=(float*)sym(d_xffn);
    float *p_y=(float*)sym(d_y), *p_ysh=(float*)sym(d_ysh);

    // fork conversions onto sA
    cudaEventRecord(evF, 0);
    cudaStreamWaitEvent(sA, evF, 0);
    conv_hilo_kernel<<<2048, 256, 0, sA>>>((const float4*)attn_w, (uint2*)p_aw_h, (uint2*)p_aw_l,
                                           (size_t)3 * D_ * D_ / 4);
    cudaEventRecord(evAW, sA);
    conv_hilo_kernel<<<1024, 256, 0, sA>>>((const float4*)attn_o_w, (uint2*)p_ow_h, (uint2*)p_ow_l,
                                           (size_t)D_ * D_ / 4);
    cudaEventRecord(evOW, sA);
    conv_hilo_ilv_kernel<<<2048, 256, 0, sA>>>((const float4*)ffn_up_w, (uint2*)p_uw_h, (uint2*)p_uw_l);
    conv_hilo_kernel<<<2048, 256, 0, sA>>>((const float4*)ffn_down_w, (uint2*)p_dw_h, (uint2*)p_dw_l,
                                           (size_t)D_ * DS_ / 4);
    conv_hilo_kernel<<<4096, 256, 0, sA>>>((const float4*)(ffn_experts + (size_t)2 * TE_ * D_ * ED_),
                                           (uint2*)p_w3_h, (uint2*)p_w3_l, (size_t)TE_ * D_ * ED_ / 4);
    transpose_w12_kernel<<<dim3(32, 16, 16), dim3(32, 8), 0, sA>>>(ffn_experts);
    cudaEventRecord(evWTS, sA);

    // attention block on stream 0 (overlaps conversions)
    rmsnorm_kernel<<<T_, 256>>>(x_input, attn_norm_w, nullptr, p_xn_h, p_xn_l);
    cudaStreamWaitEvent(0, evAW, 0);
    gemm_mma<0,0><<<dim3(24, 16), 256, GEMM_SMEM>>>(p_xn_h, p_xn_l, p_aw_h, p_aw_l,
                                                    p_qkv, nullptr, 3 * D_, D_, 0);
    rope_conv_kernel<<<S_, 256>>>(p_qkv);
    flash_attn_tc<<<dim3(S_ / 128, H_), 256, AT2_SMEM>>>(0);
    cudaStreamWaitEvent(0, evOW, 0);
    gemm_mma<0,1><<<dim3(8, 16), 256, GEMM_SMEM>>>(p_ao_h, p_ao_l, p_ow_h, p_ow_l,
                                                   p_xffn_in, x_input, D_, D_, 0);

    // ffn norm, then fork expert branch to sB
    rmsnorm_kernel<<<T_, 256>>>(p_xffn_in, ffn_norm_w, p_xffn, p_xf_h, p_xf_l);
    cudaStreamWaitEvent(0, evWTS, 0);
    cudaEventRecord(evX, 0);
    cudaStreamWaitEvent(sB, evX, 0);

    // sB: routed-expert chain (gemm1 fused swiglu, gemm2 fused combine via atomics)
    router_kernel<<<T_, 32, 0, sB>>>(p_xffn, main_keys, indices, values, main_bias);
    zero_counts_kernel<<<1, 32, 0, sB>>>();
    scatter_kernel<<<(NSLOT + 255) / 256, 256, 0, sB>>>(indices);
    cudaMemsetAsync(p_y, 0, (size_t)T_ * D_ * sizeof(float), sB);
    gemm_mma<1,2><<<dim3(8, NSLOT / 128, TE_), 256, GEMM_SMEM, sB>>>(
        p_xf_h, p_xf_l, p_w12_h, p_w12_l, (float*)p_g_h, (const float*)p_g_l,
        1024, 1024, (long long)1024 * 1024);
    gemm_mma<2,3><<<dim3(8, NSLOT / 128, TE_), 256, GEMM_SMEM, sB>>>(
        p_g_h, p_g_l, p_w3_h, p_w3_l, p_y, nullptr, 1024, 512, (long long)D_ * ED_);
    cudaEventRecord(evB, sB);

    // stream 0: shared-expert chain (up fused with swiglu -> gs hi/lo)
    gemm_mma<0,2><<<dim3(32, 16), 256, GEMM_SMEM>>>(p_xf_h, p_xf_l, p_uw_h, p_uw_l,
                                                    (float*)p_gs_h, (const float*)p_gs_l,
                                                    2 * DS_, D_, 0);
    gemm_mma<0,0><<<dim3(8, 16), 256, GEMM_SMEM>>>(p_gs_h, p_gs_l, p_dw_h, p_dw_l,
                                                   p_ysh, nullptr, D_, DS_, 0);

    // join and final combine
    cudaStreamWaitEvent(0, evB, 0);
    final_kernel<<<T_, 256>>>(shared_norm_w, output_coeff, out);
}